// round 1
// baseline (speedup 1.0000x reference)
#include <cuda_runtime.h>

// AntiAliasInterpolation2d: depthwise 13x13 Gaussian (pad 6) + bilinear x0.25.
// Fused: bilinear@0.25 is exactly 0.5/0.5 between rows 4j+1 and 4j+2 (no clip),
// so fold the 2x2 average into the separable Gaussian -> 14-tap kernel, stride 4.
// Separable factors recovered exactly from the normalized 2D weight by row/col sums.

#define IH 512
#define IW 512
#define NC 3
#define KS 13
#define OH 128
#define OW 128
#define TH 16                    // output rows per block
#define IN_ROWS (4 * TH + 10)    // 74 input rows needed per strip
#define NTHREADS 256

__device__ float g_eh[NC][14];   // width factor (effective 14-tap)
__device__ float g_ev[NC][14];   // height factor

__global__ void build_factors_kernel(const float* __restrict__ w) {
    __shared__ float k2[NC][KS][KS];
    __shared__ float rowsum[NC][KS];
    __shared__ float colsum[NC][KS];
    int t = threadIdx.x;
    for (int i = t; i < NC * KS * KS; i += blockDim.x)
        ((float*)k2)[i] = w[i];
    __syncthreads();
    if (t < NC * KS) {
        int c = t / KS, i = t % KS;
        float rs = 0.f, cs = 0.f;
#pragma unroll
        for (int j = 0; j < KS; ++j) {
            rs += k2[c][i][j];   // sum over width  -> height factor
            cs += k2[c][j][i];   // sum over height -> width factor
        }
        rowsum[c][i] = rs;
        colsum[c][i] = cs;
    }
    __syncthreads();
    if (t < NC * 14) {
        int c = t / 14, u = t % 14;
        float va = (u < KS) ? rowsum[c][u] : 0.f;
        float vb = (u >= 1) ? rowsum[c][u - 1] : 0.f;
        g_ev[c][u] = 0.5f * (va + vb);
        float ha = (u < KS) ? colsum[c][u] : 0.f;
        float hb = (u >= 1) ? colsum[c][u - 1] : 0.f;
        g_eh[c][u] = 0.5f * (ha + hb);
    }
}

__global__ __launch_bounds__(NTHREADS) void aa_interp_kernel(
    const float* __restrict__ x, float* __restrict__ out) {
    const int strip = blockIdx.x;          // which 16-row output strip
    const int img   = blockIdx.y;          // n*C + c  (0..95)
    const int c     = img % NC;
    const int i0    = strip * TH;          // first output row of strip
    const float* __restrict__ xin = x + (size_t)img * IH * IW;

    __shared__ float hbuf[IN_ROWS][OW];    // horizontally-reduced rows (38 KB)
    __shared__ float eh[14], ev[14];

    const int tid = threadIdx.x;
    if (tid < 14) {
        eh[tid] = g_eh[c][tid];
        ev[tid] = g_ev[c][tid];
    }
    __syncthreads();

    // ---- horizontal pass: global -> smem (stride-4, 14 taps, zero-pad edges)
    for (int idx = tid; idx < IN_ROWS * OW; idx += NTHREADS) {
        const int u = idx >> 7;            // local input row 0..73
        const int j = idx & (OW - 1);      // output col
        const int r = 4 * i0 - 5 + u;      // global input row
        float s = 0.f;
        if (r >= 0 && r < IH) {
            const float* __restrict__ row = xin + (size_t)r * IW;
            const int cb = 4 * j - 5;
#pragma unroll
            for (int v = 0; v < 14; ++v) {
                const int cc = cb + v;
                const float val = (cc >= 0 && cc < IW) ? __ldg(row + cc) : 0.f;
                s += val * eh[v];
            }
        }
        hbuf[u][j] = s;
    }
    __syncthreads();

    // ---- vertical pass: smem -> global (stride-4, 14 taps)
    for (int idx = tid; idx < TH * OW; idx += NTHREADS) {
        const int i = idx >> 7;            // local output row 0..15
        const int j = idx & (OW - 1);
        float s = 0.f;
#pragma unroll
        for (int u = 0; u < 14; ++u)
            s += hbuf[4 * i + u][j] * ev[u];
        out[(size_t)img * OH * OW + (size_t)(i0 + i) * OW + j] = s;
    }
}

extern "C" void kernel_launch(void* const* d_in, const int* in_sizes, int n_in,
                              void* d_out, int out_size) {
    const float* x = (const float*)d_in[0];
    const float* w = (const float*)d_in[1];
    float* out = (float*)d_out;

    const int nimg = in_sizes[0] / (IH * IW);   // 32*3 = 96

    build_factors_kernel<<<1, 128>>>(w);
    dim3 grid(OH / TH, nimg);
    aa_interp_kernel<<<grid, NTHREADS>>>(x, out);
}

// round 2
// speedup vs baseline: 2.4251x; 2.4251x over previous
#include <cuda_runtime.h>

// AntiAliasInterpolation2d: depthwise 13x13 Gaussian (pad 6) + bilinear x0.25.
// Fused: bilinear@0.25 is exactly 0.5/0.5 between rows/cols 4j+1,4j+2 (no clip),
// folded into the separable Gaussian -> effective 14-tap kernel applied stride 4.
// Separable factors recovered exactly from the normalized 2D weight by row/col sums.
//
// R2: horizontal pass is register-resident per warp-row (vector loads + shuffles
// for halo) to kill the L1 wavefront bottleneck seen in R1 (L1=69.5%, DRAM=17%).

#define IH 512
#define IW 512
#define NC 3
#define KS 13
#define OH 128
#define OW 128
#define TH 16                    // output rows per block
#define IN_ROWS (4 * TH + 10)    // 74 input rows per strip
#define NTHREADS 256

__device__ float g_eh[NC][14];   // width factor (effective 14-tap)
__device__ float g_ev[NC][14];   // height factor

__global__ void build_factors_kernel(const float* __restrict__ w) {
    __shared__ float k2[NC][KS][KS];
    __shared__ float rowsum[NC][KS];
    __shared__ float colsum[NC][KS];
    int t = threadIdx.x;
    for (int i = t; i < NC * KS * KS; i += blockDim.x)
        ((float*)k2)[i] = w[i];
    __syncthreads();
    if (t < NC * KS) {
        int c = t / KS, i = t % KS;
        float rs = 0.f, cs = 0.f;
#pragma unroll
        for (int j = 0; j < KS; ++j) {
            rs += k2[c][i][j];   // sum over width  -> height factor
            cs += k2[c][j][i];   // sum over height -> width factor
        }
        rowsum[c][i] = rs;
        colsum[c][i] = cs;
    }
    __syncthreads();
    if (t < NC * 14) {
        int c = t / 14, u = t % 14;
        float va = (u < KS) ? rowsum[c][u] : 0.f;
        float vb = (u >= 1) ? rowsum[c][u - 1] : 0.f;
        g_ev[c][u] = 0.5f * (va + vb);
        float ha = (u < KS) ? colsum[c][u] : 0.f;
        float hb = (u >= 1) ? colsum[c][u - 1] : 0.f;
        g_eh[c][u] = 0.5f * (ha + hb);
    }
}

__global__ __launch_bounds__(NTHREADS) void aa_interp_kernel(
    const float* __restrict__ x, float* __restrict__ out) {
    const int strip = blockIdx.x;            // 16-row output strip
    const int img   = blockIdx.y;            // n*C + c  (0..95)
    const int c     = img % NC;
    const int i0    = strip * TH;

    __shared__ float4 hbuf[IN_ROWS][OW / 4]; // horizontally-reduced rows (38 KB)
    __shared__ float eh[14], ev[14];

    const int tid  = threadIdx.x;
    const int warp = tid >> 5;
    const int lane = tid & 31;

    if (tid < 14) {
        eh[tid] = g_eh[c][tid];
        ev[tid] = g_ev[c][tid];
    }
    __syncthreads();

    const float4* __restrict__ xin4 =
        (const float4*)(x + (size_t)img * IH * IW);

    // ---- horizontal pass: one warp per input row, register-resident conv ----
    for (int u = warp; u < IN_ROWS; u += NTHREADS / 32) {
        const int r = 4 * i0 - 5 + u;        // global input row
        float4 o;
        if (r < 0 || r >= IH) {
            o = make_float4(0.f, 0.f, 0.f, 0.f);
        } else {
            const float4* __restrict__ row4 = xin4 + (size_t)r * (IW / 4);
            // lane L holds cols 16L..16L+15
            float4 a0 = row4[4 * lane + 0];
            float4 a1 = row4[4 * lane + 1];
            float4 a2 = row4[4 * lane + 2];
            float4 a3 = row4[4 * lane + 3];
            // halo: 5 left (from lane-1 regs 11..15), 5 right (lane+1 regs 0..4)
            float l0 = __shfl_up_sync(0xFFFFFFFFu, a2.w, 1);
            float l1 = __shfl_up_sync(0xFFFFFFFFu, a3.x, 1);
            float l2 = __shfl_up_sync(0xFFFFFFFFu, a3.y, 1);
            float l3 = __shfl_up_sync(0xFFFFFFFFu, a3.z, 1);
            float l4 = __shfl_up_sync(0xFFFFFFFFu, a3.w, 1);
            float r0 = __shfl_down_sync(0xFFFFFFFFu, a0.x, 1);
            float r1 = __shfl_down_sync(0xFFFFFFFFu, a0.y, 1);
            float r2 = __shfl_down_sync(0xFFFFFFFFu, a0.z, 1);
            float r3 = __shfl_down_sync(0xFFFFFFFFu, a0.w, 1);
            float r4 = __shfl_down_sync(0xFFFFFFFFu, a1.x, 1);
            if (lane == 0)  { l0 = l1 = l2 = l3 = l4 = 0.f; }  // zero-pad left
            if (lane == 31) { r0 = r1 = r2 = r3 = r4 = 0.f; }  // zero-pad right
            float in[26] = { l0, l1, l2, l3, l4,
                             a0.x, a0.y, a0.z, a0.w,
                             a1.x, a1.y, a1.z, a1.w,
                             a2.x, a2.y, a2.z, a2.w,
                             a3.x, a3.y, a3.z, a3.w,
                             r0, r1, r2, r3, r4 };
            // outputs j = 4*lane + q, q=0..3 ; out[q] = sum_v eh[v]*in[4q+v]
            float s0 = 0.f, s1 = 0.f, s2 = 0.f, s3 = 0.f;
#pragma unroll
            for (int v = 0; v < 14; ++v) {
                const float wv = eh[v];
                s0 += in[v]      * wv;
                s1 += in[v + 4]  * wv;
                s2 += in[v + 8]  * wv;
                s3 += in[v + 12] * wv;
            }
            o = make_float4(s0, s1, s2, s3);
        }
        hbuf[u][lane] = o;                   // contiguous STS.128, conflict-free
    }
    __syncthreads();

    // ---- vertical pass: float4 lanes across width, 2 output rows/thread ----
    const int jq = tid & 31;                 // float4 column 0..31
    const int ib = tid >> 5;                 // 0..7
    float* __restrict__ obase = out + (size_t)img * OH * OW;
#pragma unroll
    for (int half = 0; half < 2; ++half) {
        const int i = ib + 8 * half;         // local output row 0..15
        float4 acc = make_float4(0.f, 0.f, 0.f, 0.f);
#pragma unroll
        for (int u = 0; u < 14; ++u) {
            const float wv = ev[u];
            const float4 v = hbuf[4 * i + u][jq];   // contiguous LDS.128
            acc.x += v.x * wv;
            acc.y += v.y * wv;
            acc.z += v.z * wv;
            acc.w += v.w * wv;
        }
        ((float4*)(obase + (size_t)(i0 + i) * OW))[jq] = acc;
    }
}

extern "C" void kernel_launch(void* const* d_in, const int* in_sizes, int n_in,
                              void* d_out, int out_size) {
    const float* x = (const float*)d_in[0];
    const float* w = (const float*)d_in[1];
    float* out = (float*)d_out;

    const int nimg = in_sizes[0] / (IH * IW);   // 32*3 = 96

    build_factors_kernel<<<1, 128>>>(w);
    dim3 grid(OH / TH, nimg);
    aa_interp_kernel<<<grid, NTHREADS>>>(x, out);
}

// round 3
// speedup vs baseline: 2.9650x; 1.2226x over previous
#include <cuda_runtime.h>

// AntiAliasInterpolation2d: depthwise 13x13 Gaussian (pad 6) + bilinear x0.25,
// folded into an effective separable 14-tap kernel applied at stride 4.
// R3: vertical-first streaming conv straight from global (rotating accumulators,
// software-pipelined loads), then horizontal conv from smem. No shuffles.

#define IH 512
#define IW 512
#define NC 3
#define KS 13
#define OH 128
#define OW 128
#define TH 16                    // output rows per strip
#define NT 128                   // threads per block (one float4 column each)
#define VB_W (OW + 4)            // vbuf width in float4 (2 zero pads each side)

__device__ float g_eh[NC][14];   // width factor (effective 14-tap)
__device__ float g_ev[NC][14];   // height factor

__global__ void build_factors_kernel(const float* __restrict__ w) {
    __shared__ float k2[NC][KS][KS];
    __shared__ float rowsum[NC][KS];
    __shared__ float colsum[NC][KS];
    int t = threadIdx.x;
    for (int i = t; i < NC * KS * KS; i += blockDim.x)
        ((float*)k2)[i] = w[i];
    __syncthreads();
    if (t < NC * KS) {
        int c = t / KS, i = t % KS;
        float rs = 0.f, cs = 0.f;
#pragma unroll
        for (int j = 0; j < KS; ++j) {
            rs += k2[c][i][j];   // sum over width  -> height factor
            cs += k2[c][j][i];   // sum over height -> width factor
        }
        rowsum[c][i] = rs;
        colsum[c][i] = cs;
    }
    __syncthreads();
    if (t < NC * 14) {
        int c = t / 14, u = t % 14;
        float va = (u < KS) ? rowsum[c][u] : 0.f;
        float vb = (u >= 1) ? rowsum[c][u - 1] : 0.f;
        g_ev[c][u] = 0.5f * (va + vb);
        float ha = (u < KS) ? colsum[c][u] : 0.f;
        float hb = (u >= 1) ? colsum[c][u - 1] : 0.f;
        g_eh[c][u] = 0.5f * (ha + hb);
    }
}

__device__ __forceinline__ void fma4(float4& a, const float4 v, const float w) {
    a.x += v.x * w; a.y += v.y * w; a.z += v.z * w; a.w += v.w * w;
}

__global__ __launch_bounds__(NT, 6) void aa_interp_kernel(
    const float* __restrict__ x, float* __restrict__ out) {
    const int strip = blockIdx.x;          // 16-row output strip (0..7)
    const int img   = blockIdx.y;          // n*C + c (0..95)
    const int c     = img % NC;
    const int i0    = strip * TH;
    const int t     = threadIdx.x;         // float4 column 0..127

    __shared__ float4 vbuf[TH][VB_W];      // vertically-reduced rows (33.8 KB)

    // zero side pads (2 float4 each side per row)
    if (t < TH) {
        const float4 z = make_float4(0.f, 0.f, 0.f, 0.f);
        vbuf[t][0] = z; vbuf[t][1] = z;
        vbuf[t][VB_W - 2] = z; vbuf[t][VB_W - 1] = z;
    }

    float ev[14];
#pragma unroll
    for (int v = 0; v < 14; ++v) ev[v] = g_ev[c][v];

    const float4* __restrict__ xin4 =
        (const float4*)x + (size_t)img * IH * (IW / 4);
    const int rbase = 4 * i0 - 5;

    const float4 z4 = make_float4(0.f, 0.f, 0.f, 0.f);
    float4 A0 = z4, A1 = z4, A2 = z4, A3 = z4;

#define LDROW(u_) (((unsigned)(rbase + (u_)) < (unsigned)IH) \
        ? __ldg(xin4 + (size_t)(rbase + (u_)) * (IW / 4) + t) : z4)

    // software-pipelined streaming vertical conv, 4 rows per batch
    float4 n0 = LDROW(0), n1 = LDROW(1), n2 = LDROW(2), n3 = LDROW(3);
#pragma unroll
    for (int b = 0; b <= 18; ++b) {
        const float4 c0 = n0, c1 = n1, c2 = n2, c3 = n3;
        if (b < 18) {
            const int u = 4 * b + 4;
            n0 = LDROW(u); n1 = LDROW(u + 1); n2 = LDROW(u + 2); n3 = LDROW(u + 3);
        }
        // row 4b+0: taps 0,4,8,12 -> outputs b, b-1, b-2, b-3
        fma4(A0, c0, ev[0]); fma4(A1, c0, ev[4]);
        fma4(A2, c0, ev[8]); fma4(A3, c0, ev[12]);
        // row 4b+1: taps 1,5,9,13
        fma4(A0, c1, ev[1]); fma4(A1, c1, ev[5]);
        fma4(A2, c1, ev[9]); fma4(A3, c1, ev[13]);
        if (b >= 3) vbuf[b - 3][t + 2] = A3;     // output row b-3 complete
        // row 4b+2: taps 2,6,10
        fma4(A0, c2, ev[2]); fma4(A1, c2, ev[6]); fma4(A2, c2, ev[10]);
        // row 4b+3: taps 3,7,11
        fma4(A0, c3, ev[3]); fma4(A1, c3, ev[7]); fma4(A2, c3, ev[11]);
        // rotate (renamed away by full unroll)
        A3 = A2; A2 = A1; A1 = A0; A0 = z4;
    }
#undef LDROW
    __syncthreads();

    // horizontal pass from smem: output col j = t, rows 0..15
    float eh[14];
#pragma unroll
    for (int v = 0; v < 14; ++v) eh[v] = g_eh[c][v];

    float* __restrict__ obase =
        out + (size_t)img * OH * OW + (size_t)i0 * OW + t;
#pragma unroll
    for (int i = 0; i < TH; ++i) {
        const float4 w0 = vbuf[i][t];
        const float4 w1 = vbuf[i][t + 1];
        const float4 w2 = vbuf[i][t + 2];
        const float4 w3 = vbuf[i][t + 3];
        const float4 w4 = vbuf[i][t + 4];
        const float win[20] = { w0.x, w0.y, w0.z, w0.w,
                                w1.x, w1.y, w1.z, w1.w,
                                w2.x, w2.y, w2.z, w2.w,
                                w3.x, w3.y, w3.z, w3.w,
                                w4.x, w4.y, w4.z, w4.w };
        float s = 0.f;
#pragma unroll
        for (int v = 0; v < 14; ++v) s += win[v + 3] * eh[v];
        obase[(size_t)i * OW] = s;
    }
}

extern "C" void kernel_launch(void* const* d_in, const int* in_sizes, int n_in,
                              void* d_out, int out_size) {
    const float* x = (const float*)d_in[0];
    const float* w = (const float*)d_in[1];
    float* out = (float*)d_out;

    const int nimg = in_sizes[0] / (IH * IW);   // 32*3 = 96

    build_factors_kernel<<<1, 128>>>(w);
    dim3 grid(OH / TH, nimg);
    aa_interp_kernel<<<grid, NT>>>(x, out);
}